// round 9
// baseline (speedup 1.0000x reference)
#include <cuda_runtime.h>
#include <math.h>

// Problem constants
#define NPTS   2048
#define NNODES 8192
#define NCMP   1024
#define NWORDS 256           // NNODES / 32
#define THRESH 2.2f         // tier-2 threshold (mean ~114 cands/row total)
#define T1     3.0f         // tier-1 threshold (mean ~11.1 cands/row)
#define T1CAP  64           // tier-1 capacity (Poisson(11): P(>64) ~ 0)
#define T2CAP  160          // tier-2 capacity (mean ~103, sigma ~10)
#define CAP    (T1CAP + T2CAP)   // 224 slots/row

// Scratch (__device__ globals). g_bits is w-major: g_bits[w][c].
__device__ unsigned int       g_bits[NWORDS * NCMP];      // 1 MB
__device__ unsigned long long g_cand[(size_t)NPTS * CAP]; // {val:hi32, idx:lo32}; tier1 @0, tier2 @64
__device__ int2               g_cnt12[NPTS];              // {cnt1, cnt2}; -1 = overflow

// ---------------------------------------------------------------------------
// Fused kernel A+B. Grid 2560: bid%5==4 -> pack block (512 total, interleaved
// so pack's DRAM stream overlaps B); else select block (one row each).
//
// Select: lane-private two-tier classification; unordered scatter into the
// row's tier buckets via smem atomic counters. NO sort, no staging epilogue —
// kernel C max-combines over hits, so order is irrelevant (exact + determin.).
// ---------------------------------------------------------------------------
__global__ __launch_bounds__(256) void ab_kernel(const float* __restrict__ x,
                                                 const int* __restrict__ mask) {
    int bid = blockIdx.x;
    if ((bid % 5) == 4) {
        // ---- pack block (R2 form, measured best) ----
        int warp = threadIdx.x >> 5;
        int lane = threadIdx.x & 31;
        int task = (bid / 5) * 8 + warp;   // 0..4095
        int w    = task >> 4;
        int cg   = task & 15;
        int c0   = cg * 64 + lane * 2;
        int n0   = w * 32;

        unsigned b0 = 0, b1 = 0;
        const int* base = mask + (size_t)n0 * NCMP + c0;
        #pragma unroll
        for (int i = 0; i < 32; i++) {
            int2 v = *(const int2*)(base + (size_t)i * NCMP);
            b0 |= (unsigned)(v.x != 0) << i;
            b1 |= (unsigned)(v.y != 0) << i;
        }
        uint2 o; o.x = b0; o.y = b1;
        *(uint2*)(g_bits + (size_t)w * NCMP + c0) = o;
        return;
    }

    // ---- select block ----
    __shared__ int s_c1, s_c2;

    int p   = bid - bid / 5;               // 0..2047
    int tid = threadIdx.x;
    if (tid == 0) { s_c1 = 0; s_c2 = 0; }
    __syncthreads();

    unsigned long long* cand = g_cand + (size_t)p * CAP;
    const float4* row4 = (const float4*)(x + (size_t)p * NNODES);
    #pragma unroll
    for (int i = 0; i < NNODES / (256 * 4); i++) {       // 8 passes
        int q = tid + 256 * i;
        float4 v = row4[q];
        float m = fmaxf(fmaxf(v.x, v.y), fmaxf(v.z, v.w));
        if (m > THRESH) {                                // ~1.7 lanes/warp-pass
            int n = q * 4;
            #define HANDLE(comp, nn)                                              \
                if ((comp) > THRESH) {                                            \
                    unsigned long long e =                                        \
                        ((unsigned long long)__float_as_uint(comp) << 32) |       \
                        (unsigned)(nn);                                           \
                    if ((comp) > T1) {                                            \
                        int pos = atomicAdd(&s_c1, 1);                            \
                        if (pos < T1CAP) cand[pos] = e;                           \
                    } else {                                                      \
                        int pos = atomicAdd(&s_c2, 1);                            \
                        if (pos < T2CAP) cand[T1CAP + pos] = e;                   \
                    }                                                             \
                }
            HANDLE(v.x, n) HANDLE(v.y, n + 1) HANDLE(v.z, n + 2) HANDLE(v.w, n + 3)
            #undef HANDLE
        }
    }
    __syncthreads();

    if (tid == 0) {
        int c1 = s_c1, c2 = s_c2;
        int2 o;
        o.x = (c1 > T1CAP) ? -1 : c1;      // tier-1 overflow -> full fallback
        o.y = (c2 > T2CAP) ? -1 : c2;      // tier-2 overflow -> fallback if t1 missed
        g_cnt12[p] = o;
    }
}

// ---------------------------------------------------------------------------
// Kernel C: masked column max by max-combining over candidate hits.
// No bitset tile: a probe = one coalesced 128B LDG of g_bits[w][c0..c0+31]
// (L1-hot, ~32KB working set per block). smem = 17KB -> ~2x occupancy vs R8.
// Tier-1 (first 16 staged in smem) -> tier-2 (global, 1.4% of warp-rows) ->
// full bitset scan (rare: overflow / all-miss / empty column -> 0.0).
// Max-combining is order-free and strictly additive (tier2 values < tier1
// values <= true max), so later stages can always fold into res.
// ---------------------------------------------------------------------------
#define TC    32
#define TPR   128
#define STAGE 16

__global__ __launch_bounds__(256) void masked_colmax_kernel(const float* __restrict__ x,
                                                            float* __restrict__ out) {
    __shared__ unsigned long long s_cs[TPR * STAGE];     // 16 KB: first 16 tier-1/row
    __shared__ int2               s_cnt[TPR];            // 1 KB

    int c0 = blockIdx.x * TC;
    int p0 = blockIdx.y * TPR;

    if (threadIdx.x < TPR) s_cnt[threadIdx.x] = g_cnt12[p0 + threadIdx.x];
    #pragma unroll
    for (int k = 0; k < (TPR * STAGE) / 256; k++) {      // 8 passes, coalesced
        int idx  = threadIdx.x + 256 * k;
        int r    = idx >> 4;
        int slot = idx & (STAGE - 1);
        s_cs[idx] = g_cand[(size_t)(p0 + r) * CAP + slot];
    }
    __syncthreads();

    int cl = threadIdx.x & 31;
    int pr = threadIdx.x >> 5;
    const unsigned int* bitc = g_bits + c0 + cl;         // + w*NCMP per probe

    for (int r = pr; r < TPR; r += 8) {
        int p = p0 + r;
        int2 cc = s_cnt[r];                              // warp-uniform
        int cnt1 = cc.x, cnt2 = cc.y;
        float res = -INFINITY;

        // PROBE: test candidate e against this lane's column, fold max.
        #define PROBE(e, live)                                                    \
            {                                                                     \
                unsigned _i = (unsigned)(e) & (NNODES - 1);                       \
                unsigned _w = bitc[(_i >> 5) * NCMP];                             \
                bool _h = (live) && ((_w >> (_i & 31u)) & 1u);                    \
                res = fmaxf(res, _h ? __uint_as_float((unsigned)((e) >> 32))      \
                                    : -INFINITY);                                 \
            }

        if (cnt1 >= 0) {
            const unsigned long long* cs = s_cs + r * STAGE;
            int ns = cnt1 < STAGE ? cnt1 : STAGE;
            #pragma unroll 1
            for (int k = 0; k < ns; k += 4) {            // 4 independent probes
                unsigned long long e0 = cs[k], e1 = cs[k + 1];
                unsigned long long e2 = cs[k + 2], e3 = cs[k + 3];
                PROBE(e0, true) PROBE(e1, k + 1 < ns) PROBE(e2, k + 2 < ns) PROBE(e3, k + 3 < ns)
            }
            const unsigned long long* cg = g_cand + (size_t)p * CAP;
            #pragma unroll 1
            for (int k = STAGE; k < cnt1; k += 4) {      // P(cnt1>16) ~ 5%
                unsigned long long e0 = cg[k], e1 = cg[k + 1];
                unsigned long long e2 = cg[k + 2], e3 = cg[k + 3];
                PROBE(e0, true) PROBE(e1, k + 1 < cnt1) PROBE(e2, k + 2 < cnt1) PROBE(e3, k + 3 < cnt1)
            }
        }

        if (__any_sync(0xFFFFFFFFu, res == -INFINITY)) {
            if (cnt1 >= 0 && cnt2 >= 0) {                // tier-2 sweep (~1.4%)
                const unsigned long long* cg = g_cand + (size_t)p * CAP + T1CAP;
                #pragma unroll 1
                for (int k = 0; k < cnt2; k += 4) {
                    unsigned long long e0 = cg[k], e1 = cg[k + 1];
                    unsigned long long e2 = cg[k + 2], e3 = cg[k + 3];
                    PROBE(e0, true) PROBE(e1, k + 1 < cnt2) PROBE(e2, k + 2 < cnt2) PROBE(e3, k + 3 < cnt2)
                }
            }
            if (__any_sync(0xFFFFFFFFu, res == -INFINITY)) {
                // Full exact scan (overflow rows / all-miss / empty columns).
                const float* row = x + (size_t)p * NNODES;
                for (int w = 0; w < NWORDS; w++) {
                    unsigned int b = bitc[w * NCMP];
                    while (b) {
                        int bit = __ffs(b) - 1;
                        res = fmaxf(res, row[w * 32 + bit]);
                        b &= b - 1;
                    }
                }
            }
        }
        #undef PROBE

        out[(size_t)p * NCMP + (c0 + cl)] = (res == -INFINITY) ? 0.0f : res;
    }
}

// ---------------------------------------------------------------------------
extern "C" void kernel_launch(void* const* d_in, const int* in_sizes, int n_in,
                              void* d_out, int out_size) {
    const float* x;
    const int*   mask;
    if (in_sizes[0] == NPTS * NNODES) {    // metadata order: x, learned_edge_states
        x    = (const float*)d_in[0];
        mask = (const int*)d_in[1];
    } else {
        x    = (const float*)d_in[1];
        mask = (const int*)d_in[0];
    }
    float* out = (float*)d_out;

    ab_kernel<<<2560, 256>>>(x, mask);     // pack + tiered select, overlapped
    masked_colmax_kernel<<<dim3(NCMP / TC, NPTS / TPR), 256>>>(x, out);
}